// round 16
// baseline (speedup 1.0000x reference)
#include <cuda_runtime.h>
#include <cuda_bf16.h>
#include <cuda_fp16.h>
#include <cstdint>
#include <cstddef>

#define NN 40000
#define EE 60000
#define RR 6
#define ETOT (EE + NN)          // 100000 edges per relation incl self-loops
#define RN (RR * NN)            // 240000
#define HC 256                  // H*C
#define HID 128
#define BGRAPH 2000
#define SCAN_NB ((RN + 1023) / 1024)   // 235
#define BM 64
#define BN 128
#define WSTH 40                 // W stage row stride in halves (32 k + 8 pad)
#define WSTAGEB (BN * WSTH * 2) // bytes per W pipeline stage (10240)
// dynamic smem upper bound: X tile (F=128, halves) + 3 W stages
#define GEMM_SMEM (BM * 136 * 2 + 3 * WSTAGEB)   // 48128 bytes
#define TILES_A 320             // layer-2 pipeline chunk A (nodes 0..20480)
#define TILES_B 305             // chunk B (nodes 20480..40000)

// ---------------- scratch (static device globals; no runtime allocation) ----
static __device__ __half2 g_XLh[RN * 128];   // [R][N][128] half2 (256 vals)
static __device__ __half2 g_XRh[RN * 128];   // [R][N][128] half2 (256 vals)
static __device__ float g_H[NN * HID];       // final node features (layer 2)
static __device__ __half2 g_Xch[NN * 64];    // GEMM input [N][128] as half2
static __device__ __half  g_Wch[12 * HC * HID]; // fp16 W, [rs][n][k]
static __device__ int   g_counts[RN];
static __device__ int   g_offsets[RN];
static __device__ int   g_cursor[RN];
static __device__ int   g_srcs[RR * ETOT];
static __device__ int   g_bsum[SCAN_NB];

// ---------------- CSR construction -----------------------------------------
__global__ void k_init_counts() {
    int i = blockIdx.x * blockDim.x + threadIdx.x;
    if (i < RN) g_counts[i] = 1;          // 1 == self-loop
}

__global__ void k_hist(const int* __restrict__ ei) {
    int i = blockIdx.x * blockDim.x + threadIdx.x;
    if (i >= RR * EE) return;
    int r = i / EE, e = i - r * EE;
    int dst = ei[(r * 2 + 1) * EE + e];
    atomicAdd(&g_counts[r * NN + dst], 1);
}

__global__ void k_scan1() {
    __shared__ int wsum[8];
    int tid = threadIdx.x;
    int i0 = blockIdx.x * 1024 + tid * 4;
    int4 v = make_int4(0, 0, 0, 0);
    bool ok = (i0 < RN);
    if (ok) v = *(const int4*)&g_counts[i0];
    int s0 = v.x, s1 = s0 + v.y, s2 = s1 + v.z, s3 = s2 + v.w;
    int lane = tid & 31, w = tid >> 5;
    int sc = s3;
#pragma unroll
    for (int off = 1; off < 32; off <<= 1) {
        int t = __shfl_up_sync(0xffffffffu, sc, off);
        if (lane >= off) sc += t;
    }
    if (lane == 31) wsum[w] = sc;
    __syncthreads();
    if (tid == 0) {
        int run = 0;
#pragma unroll
        for (int j = 0; j < 8; j++) { int t = wsum[j]; wsum[j] = run; run += t; }
        g_bsum[blockIdx.x] = run;
    }
    __syncthreads();
    int excl = wsum[w] + sc - s3;
    if (ok) {
        g_offsets[i0 + 0] = excl;
        g_offsets[i0 + 1] = excl + s0;
        g_offsets[i0 + 2] = excl + s1;
        g_offsets[i0 + 3] = excl + s2;
    }
}

__global__ void k_scan2() {
    __shared__ int wsum[8];
    int tid = threadIdx.x;
    int v = (tid < SCAN_NB) ? g_bsum[tid] : 0;
    int lane = tid & 31, w = tid >> 5;
    int s = v;
#pragma unroll
    for (int off = 1; off < 32; off <<= 1) {
        int t = __shfl_up_sync(0xffffffffu, s, off);
        if (lane >= off) s += t;
    }
    if (lane == 31) wsum[w] = s;
    __syncthreads();
    if (tid == 0) {
        int run = 0;
#pragma unroll
        for (int j = 0; j < 8; j++) { int t = wsum[j]; wsum[j] = run; run += t; }
    }
    __syncthreads();
    int excl = wsum[w] + s - v;
    if (tid < SCAN_NB) g_bsum[tid] = excl;
}

__global__ void k_scan3() {
    int i0 = blockIdx.x * 1024 + threadIdx.x * 4;
    if (i0 >= RN) return;
    int base = g_bsum[blockIdx.x];
    int4 o = *(const int4*)&g_offsets[i0];
    o.x += base; o.y += base; o.z += base; o.w += base;
    *(int4*)&g_offsets[i0] = o;
    *(int4*)&g_cursor[i0] = o;
}

__global__ void k_scatter(const int* __restrict__ ei) {
    int i = blockIdx.x * blockDim.x + threadIdx.x;
    if (i >= RR * ETOT) return;
    int r = i / ETOT, j = i - r * ETOT;
    int src, dst;
    if (j < EE) {
        src = ei[(r * 2 + 0) * EE + j];
        dst = ei[(r * 2 + 1) * EE + j];
    } else {
        src = j - EE; dst = src;        // self-loop
    }
    int pos = atomicAdd(&g_cursor[r * NN + dst], 1);
    g_srcs[pos] = src;
}

// ---------------- mma helpers -------------------------------------------------
__device__ __forceinline__ void mma16(float* d, const uint32_t* a, uint32_t b0, uint32_t b1) {
    asm volatile(
        "mma.sync.aligned.m16n8k16.row.col.f32.f16.f16.f32 "
        "{%0,%1,%2,%3}, {%4,%5,%6,%7}, {%8,%9}, {%0,%1,%2,%3};"
        : "+f"(d[0]), "+f"(d[1]), "+f"(d[2]), "+f"(d[3])
        : "r"(a[0]), "r"(a[1]), "r"(a[2]), "r"(a[3]), "r"(b0), "r"(b1));
}
__device__ __forceinline__ void cpasync16(uint32_t dst, const void* src) {
    asm volatile("cp.async.cg.shared.global [%0], [%1], 16;" :: "r"(dst), "l"(src));
}
__device__ __forceinline__ void ldsm4(uint32_t* r, uint32_t addr) {
    asm volatile("ldmatrix.sync.aligned.m8n8.x4.b16 {%0,%1,%2,%3}, [%4];"
        : "=r"(r[0]), "=r"(r[1]), "=r"(r[2]), "=r"(r[3]) : "r"(addr));
}

// ---------------- pre-conversion kernels ------------------------------------
// X fp32 -> g_Xch fp16 (layer-1 only; layer-2 input written by k_gather)
__global__ void k_cvtX(const float* __restrict__ X, int total4) {
    int i = blockIdx.x * blockDim.x + threadIdx.x;
    if (i >= total4) return;
    float4 v = *(const float4*)(X + (size_t)i * 4);
    __half2 h01 = __float22half2_rn(make_float2(v.x, v.y));
    __half2 h23 = __float22half2_rn(make_float2(v.z, v.w));
    uint2 u; u.x = *(unsigned*)&h01; u.y = *(unsigned*)&h23;
    *(uint2*)&g_Xch[(size_t)i * 2] = u;
}

// W [R][F][HC] (n contiguous) -> g_Wch [rs][n][k] (k contiguous), fp16
__global__ void k_cvtW(const float* __restrict__ Wl, const float* __restrict__ Wr, int F) {
    int i = blockIdx.x * blockDim.x + threadIdx.x;
    if (i >= 12 * HC * F) return;
    int rs = i / (HC * F);
    int rem = i - rs * (HC * F);
    int n = rem / F, k = rem - n * F;
    int r = (rs < RR) ? rs : rs - RR;
    const float* W = ((rs < RR) ? Wl : Wr) + ((size_t)r * F + k) * HC + n;
    g_Wch[i] = __float2half(*W);
}

// ---------------- fp16 GEMM, X-resident, 3-stage W pipeline, 1 sync/tile ----
__global__ __launch_bounds__(256, 2) void k_gemm(
    int F, int tileBase, const float* __restrict__ bl, const float* __restrict__ br)
{
    extern __shared__ char smemc[];
    int nhalf = blockIdx.y;
    int rowBase = (blockIdx.x + tileBase) * BM;
    const int PRXB = (F + 8) * 2;          // X tile row stride (bytes)
    const int nk = F >> 5;                 // k-tiles per slice (1 or 4)
    const int nksh = (F == 32) ? 0 : 2;
    const int cprsh = (F == 32) ? 2 : 4;   // log2(16B chunks per X row)
    const int cmask = (F >> 3) - 1;

    uint32_t sBase = (uint32_t)__cvta_generic_to_shared(smemc);
    uint32_t wBase = sBase + BM * PRXB;
    int tid = threadIdx.x, lane = tid & 31, warp = tid >> 5;
    int wm = warp >> 2, wn = warp & 3;     // 2 x 4 warps, warp tile 32m x 32n

    const __half* Xh = (const __half*)g_Xch;
    int nxc = F >> 5;   // 16B chunks per thread (1 or 4)
#pragma unroll 2
    for (int i = 0; i < nxc; i++) {
        int c = tid + i * 256;
        int row = c >> cprsh, col = c & cmask;
        cpasync16(sBase + row * PRXB + col * 16,
                  Xh + (size_t)(rowBase + row) * F + col * 8);
    }

    auto loadW = [&](int s, int t) {
        int rs12 = t >> nksh;
        int kc = (t & (nk - 1)) << 5;      // halves
        const __half* Wp = g_Wch + (size_t)rs12 * HC * F + (size_t)nhalf * BN * F + kc;
        uint32_t ws = wBase + s * WSTAGEB;
#pragma unroll
        for (int i = 0; i < 2; i++) {
            int c = tid + i * 256;
            int row = c >> 2, col = c & 3;
            cpasync16(ws + row * (WSTH * 2) + col * 16,
                      Wp + (size_t)row * F + col * 8);
        }
        asm volatile("cp.async.commit_group;");
    };

    const int total = 12 * nk;
    loadW(0, 0);
    loadW(1, 1);

    uint32_t aBase = sBase + (wm * 32 + (lane & 15)) * PRXB + (lane >> 4) * 16;
    uint32_t bBase = wBase + (wn * 32 + (lane & 7) + ((lane >> 3) & 1) * 8) * (WSTH * 2)
                     + (lane >> 4) * 16;
    int gid = lane >> 2, tg = lane & 3;

    int t = 0;
    for (int rs12 = 0; rs12 < 12; rs12++) {
        float acc[2][4][4];
#pragma unroll
        for (int a = 0; a < 2; a++)
#pragma unroll
            for (int b = 0; b < 4; b++)
#pragma unroll
                for (int c = 0; c < 4; c++) acc[a][b][c] = 0.f;

        for (int kk = 0; kk < nk; kk++, t++) {
            if (t < total - 1) asm volatile("cp.async.wait_group 1;");
            else               asm volatile("cp.async.wait_group 0;");
            __syncthreads();
            if (t + 2 < total) loadW((t + 2) % 3, t + 2);

            uint32_t aSt = aBase + kk * 64;            // kk*32 halves
            uint32_t bSt = bBase + (t % 3) * WSTAGEB;
#pragma unroll
            for (int kt = 0; kt < 2; kt++) {
                uint32_t a0[4], a1[4];
                ldsm4(a0, aSt + kt * 32);
                ldsm4(a1, aSt + kt * 32 + 16 * PRXB);
                uint32_t b[8];
                ldsm4(b,     bSt + kt * 32);
                ldsm4(b + 4, bSt + kt * 32 + 16 * (WSTH * 2));
                mma16(acc[0][0], a0, b[0], b[2]);
                mma16(acc[1][0], a1, b[0], b[2]);
                mma16(acc[0][1], a0, b[1], b[3]);
                mma16(acc[1][1], a1, b[1], b[3]);
                mma16(acc[0][2], a0, b[4], b[6]);
                mma16(acc[1][2], a1, b[4], b[6]);
                mma16(acc[0][3], a0, b[5], b[7]);
                mma16(acc[1][3], a1, b[5], b[7]);
            }
        }

        int r = (rs12 < RR) ? rs12 : rs12 - RR;
        const float* bias = ((rs12 < RR) ? bl : br) + (size_t)r * HC + nhalf * BN;
        __half2* Y = ((rs12 < RR) ? g_XLh : g_XRh)
                     + (size_t)r * NN * 128 + nhalf * (BN / 2);
#pragma unroll
        for (int mt = 0; mt < 2; mt++) {
            int gr = rowBase + wm * 32 + mt * 16 + gid;
#pragma unroll
            for (int nt = 0; nt < 4; nt++) {
                int gc = wn * 32 + nt * 8 + 2 * tg;
                float bv0 = bias[gc], bv1 = bias[gc + 1];
                __half2 h01 = __float22half2_rn(
                    make_float2(acc[mt][nt][0] + bv0, acc[mt][nt][1] + bv1));
                __half2 h23 = __float22half2_rn(
                    make_float2(acc[mt][nt][2] + bv0, acc[mt][nt][3] + bv1));
                __stcs((unsigned*)&Y[(size_t)gr * 128 + (gc >> 1)], *(unsigned*)&h01);
                __stcs((unsigned*)&Y[(size_t)(gr + 8) * 128 + (gc >> 1)], *(unsigned*)&h23);
            }
        }
    }
}

// ---------------- GATv2 gather: warp/node, 2-wide edges, no-max softmax -----
__device__ __forceinline__ float4 h4tof4(uint2 u) {
    float2 lo = __half22float2(*(__half2*)&u.x);
    float2 hi = __half22float2(*(__half2*)&u.y);
    return make_float4(lo.x, lo.y, hi.x, hi.y);
}
__device__ __forceinline__ float lr4(const float4 xl, const float4 xr, const float4 a) {
    float t, p;
    t = xl.x + xr.x; t = (t > 0.f) ? t : 0.2f * t; p = t * a.x;
    t = xl.y + xr.y; t = (t > 0.f) ? t : 0.2f * t; p = fmaf(t, a.y, p);
    t = xl.z + xr.z; t = (t > 0.f) ? t : 0.2f * t; p = fmaf(t, a.z, p);
    t = xl.w + xr.w; t = (t > 0.f) ? t : 0.2f * t; p = fmaf(t, a.w, p);
    return p;
}

// mode 0: write fp16 result to g_Xch; mode 1: write fp32 result to g_H.
__global__ __launch_bounds__(256) void k_gather(
    const float* __restrict__ att, const float* __restrict__ bias,
    const float* __restrict__ lng, const float* __restrict__ lnb,
    int mode, int nodeBase)
{
    int n = nodeBase + ((blockIdx.x * blockDim.x + threadIdx.x) >> 5);
    int lane = threadIdx.x & 31;
    if (n >= NN) return;
    float o0 = 0.f, o1 = 0.f, o2 = 0.f, o3 = 0.f;
#pragma unroll 1
    for (int r = 0; r < RR; r++) {
        const __half2* xrp = g_XRh + ((size_t)(r * NN + n)) * 128 + lane * 2;
        float4 xr0 = h4tof4(__ldcs((const uint2*)xrp));
        float4 xr1 = h4tof4(__ldcs((const uint2*)(xrp + 64)));
        const float* ap = att + (size_t)r * HC + lane * 4;
        float4 a0 = *(const float4*)ap;
        float4 a1 = *(const float4*)(ap + 128);
        int idx = r * NN + n;
        int start = g_offsets[idx];
        int deg = g_counts[idx];
        const __half2* XLr = g_XLh + (size_t)r * NN * 128;

        float s0 = 0.f, s1 = 0.f;
        float4 acc0 = make_float4(0, 0, 0, 0), acc1 = make_float4(0, 0, 0, 0);
#pragma unroll 1
        for (int e = 0; e < deg; e += 2) {
            int srcA = g_srcs[start + e];
            const __half2* pA = XLr + (size_t)srcA * 128 + lane * 2;
            float4 A0 = h4tof4(*(const uint2*)pA);
            float4 A1 = h4tof4(*(const uint2*)(pA + 64));
            bool two = (e + 1 < deg);
            float4 B0 = make_float4(0, 0, 0, 0), B1 = make_float4(0, 0, 0, 0);
            if (two) {
                int srcB = g_srcs[start + e + 1];
                const __half2* pB = XLr + (size_t)srcB * 128 + lane * 2;
                B0 = h4tof4(*(const uint2*)pB);
                B1 = h4tof4(*(const uint2*)(pB + 64));
            }
            float pa0 = lr4(A0, xr0, a0);
            float pa1 = lr4(A1, xr1, a1);
            float pb0 = two ? lr4(B0, xr0, a0) : -1e30f;
            float pb1 = two ? lr4(B1, xr1, a1) : -1e30f;
#pragma unroll
            for (int off = 16; off; off >>= 1) {
                pa0 += __shfl_xor_sync(0xffffffffu, pa0, off);
                pa1 += __shfl_xor_sync(0xffffffffu, pa1, off);
                pb0 += __shfl_xor_sync(0xffffffffu, pb0, off);
                pb1 += __shfl_xor_sync(0xffffffffu, pb1, off);
            }
            float wa0 = __expf(pa0), wa1 = __expf(pa1);
            float wb0 = __expf(pb0), wb1 = __expf(pb1);   // 0 when !two
            s0 += wa0 + wb0; s1 += wa1 + wb1;
            acc0.x += wa0 * A0.x + wb0 * B0.x;
            acc0.y += wa0 * A0.y + wb0 * B0.y;
            acc0.z += wa0 * A0.z + wb0 * B0.z;
            acc0.w += wa0 * A0.w + wb0 * B0.w;
            acc1.x += wa1 * A1.x + wb1 * B1.x;
            acc1.y += wa1 * A1.y + wb1 * B1.y;
            acc1.z += wa1 * A1.z + wb1 * B1.z;
            acc1.w += wa1 * A1.w + wb1 * B1.w;
        }
        float i0 = 0.5f / s0, i1 = 0.5f / s1;   // 0.5 == head average
        float4 bv = *(const float4*)(bias + (size_t)r * HID + lane * 4);
        o0 += acc0.x * i0 + acc1.x * i1 + bv.x;
        o1 += acc0.y * i0 + acc1.y * i1 + bv.y;
        o2 += acc0.z * i0 + acc1.z * i1 + bv.z;
        o3 += acc0.w * i0 + acc1.w * i1 + bv.w;
    }
    // fused tanh + LayerNorm over 128 channels (4 per lane)
    float t0 = tanhf(o0), t1 = tanhf(o1), t2 = tanhf(o2), t3 = tanhf(o3);
    float sum = t0 + t1 + t2 + t3;
#pragma unroll
    for (int off = 16; off; off >>= 1) sum += __shfl_xor_sync(0xffffffffu, sum, off);
    float mu = sum * (1.f / 128.f);
    float d0 = t0 - mu, d1 = t1 - mu, d2 = t2 - mu, d3 = t3 - mu;
    float vv = d0 * d0 + d1 * d1 + d2 * d2 + d3 * d3;
#pragma unroll
    for (int off = 16; off; off >>= 1) vv += __shfl_xor_sync(0xffffffffu, vv, off);
    float inv = rsqrtf(vv * (1.f / 128.f) + 1e-5f);
    float4 gg = *(const float4*)(lng + lane * 4);
    float4 bb = *(const float4*)(lnb + lane * 4);
    float4 out;
    out.x = d0 * inv * gg.x + bb.x;
    out.y = d1 * inv * gg.y + bb.y;
    out.z = d2 * inv * gg.z + bb.z;
    out.w = d3 * inv * gg.w + bb.w;
    if (mode == 0) {
        __half2 h01 = __float22half2_rn(make_float2(out.x, out.y));
        __half2 h23 = __float22half2_rn(make_float2(out.z, out.w));
        uint2 u; u.x = *(unsigned*)&h01; u.y = *(unsigned*)&h23;
        *(uint2*)&g_Xch[(size_t)n * 64 + lane * 2] = u;
    } else {
        *(float4*)&g_H[(size_t)n * HID + lane * 4] = out;
    }
}

// ---------------- attention pooling over graphs + final projection ----------
__global__ __launch_bounds__(128) void k_pool(
    const float* __restrict__ q, const float* __restrict__ W,
    const float* __restrict__ pb, float* __restrict__ out)
{
    __shared__ float hs[20][128];
    __shared__ float sc[20];
    __shared__ float ww[20];
    __shared__ float gs[128];
    int b = blockIdx.x, t = threadIdx.x;
#pragma unroll
    for (int n = 0; n < 20; n++) hs[n][t] = g_H[(size_t)(b * 20 + n) * HID + t];
    __syncthreads();
    int lane = t & 31, w = t >> 5;
    float4 q4 = *(const float4*)&q[lane * 4];
#pragma unroll
    for (int k = 0; k < 5; k++) {
        int n = w * 5 + k;
        float4 hv = *(const float4*)&hs[n][lane * 4];
        float p = hv.x * q4.x + hv.y * q4.y + hv.z * q4.z + hv.w * q4.w;
#pragma unroll
        for (int off = 16; off; off >>= 1) p += __shfl_xor_sync(0xffffffffu, p, off);
        if (lane == 0) sc[n] = p;
    }
    __syncthreads();
    if (t < 32) {
        float v = (t < 20) ? sc[t] : -1e30f;
        float m = v;
#pragma unroll
        for (int off = 16; off; off >>= 1) m = fmaxf(m, __shfl_xor_sync(0xffffffffu, m, off));
        float e = (t < 20) ? __expf(v - m) : 0.f;
        float s = e;
#pragma unroll
        for (int off = 16; off; off >>= 1) s += __shfl_xor_sync(0xffffffffu, s, off);
        if (t < 20) ww[t] = e / s;
    }
    __syncthreads();
    float g = 0.f;
#pragma unroll
    for (int n = 0; n < 20; n++) g = fmaf(ww[n], hs[n][t], g);
    gs[t] = g;
    __syncthreads();
    float o = pb[t];
#pragma unroll 8
    for (int k = 0; k < 128; k++) o = fmaf(gs[k], W[k * 128 + t], o);
    out[(size_t)b * 128 + t] = o;
}

// ---------------- launch ----------------------------------------------------
static cudaStream_t s_side = nullptr;
static cudaEvent_t  s_fork = nullptr, s_join = nullptr;
static cudaEvent_t  s_ga = nullptr, s_gb = nullptr, s_l2 = nullptr;

extern "C" void kernel_launch(void* const* d_in, const int* in_sizes, int n_in,
                              void* d_out, int out_size) {
    const float* x     = (const float*)d_in[0];
    const int*   ei    = (const int*)  d_in[1];
    const float* Wl1   = (const float*)d_in[3];
    const float* bl1   = (const float*)d_in[4];
    const float* Wr1   = (const float*)d_in[5];
    const float* br1   = (const float*)d_in[6];
    const float* att1  = (const float*)d_in[7];
    const float* bias1 = (const float*)d_in[8];
    const float* Wl2   = (const float*)d_in[9];
    const float* bl2   = (const float*)d_in[10];
    const float* Wr2   = (const float*)d_in[11];
    const float* br2   = (const float*)d_in[12];
    const float* att2  = (const float*)d_in[13];
    const float* bias2 = (const float*)d_in[14];
    const float* ln1g  = (const float*)d_in[15];
    const float* ln1b  = (const float*)d_in[16];
    const float* ln2g  = (const float*)d_in[17];
    const float* ln2b  = (const float*)d_in[18];
    const float* query = (const float*)d_in[19];
    const float* projW = (const float*)d_in[20];
    const float* projb = (const float*)d_in[21];
    float* out = (float*)d_out;

    if (!s_side) {
        cudaStreamCreateWithFlags(&s_side, cudaStreamNonBlocking);
        cudaEventCreateWithFlags(&s_fork, cudaEventDisableTiming);
        cudaEventCreateWithFlags(&s_join, cudaEventDisableTiming);
        cudaEventCreateWithFlags(&s_ga, cudaEventDisableTiming);
        cudaEventCreateWithFlags(&s_gb, cudaEventDisableTiming);
        cudaEventCreateWithFlags(&s_l2, cudaEventDisableTiming);
    }
    cudaFuncSetAttribute(k_gemm, cudaFuncAttributeMaxDynamicSharedMemorySize, GEMM_SMEM);

    int smem1 = BM * (32 + 8) * 2 + 3 * WSTAGEB;     // F=32:  35840 B
    int smem2 = BM * (128 + 8) * 2 + 3 * WSTAGEB;    // F=128: 48128 B

    // ---- main stream: layer-1 GEMM path ----
    k_cvtW<<<(12 * HC * 32 + 255) / 256, 256>>>(Wl1, Wr1, 32);       // 0
    k_cvtX<<<(NN * 32 / 4 + 255) / 256, 256>>>(x, NN * 32 / 4);      // 1

    // fork side stream (CSR build + cvtW2), fully independent of GEMM path
    cudaEventRecord(s_fork, 0);
    cudaStreamWaitEvent(s_side, s_fork, 0);
    k_init_counts<<<(RN + 255) / 256, 256, 0, s_side>>>();           // 2
    k_gemm<<<dim3(NN / BM, 2), 256, smem1>>>(32, 0, bl1, br1);       // 3 (profiled)
    k_hist<<<(RR * EE + 255) / 256, 256, 0, s_side>>>(ei);
    k_scan1<<<SCAN_NB, 256, 0, s_side>>>();
    k_scan2<<<1, 256, 0, s_side>>>();
    k_scan3<<<SCAN_NB, 256, 0, s_side>>>();
    k_scatter<<<(RR * ETOT + 255) / 256, 256, 0, s_side>>>(ei);
    k_cvtW<<<(12 * HC * 128 + 255) / 256, 256, 0, s_side>>>(Wl2, Wr2, 128);
    cudaEventRecord(s_join, s_side);

    // join: gather needs gemm1 (main) + CSR (side)
    cudaStreamWaitEvent(0, s_join, 0);

    // ---- layer-1 gather / layer-2 GEMM chunk pipeline ----
    // chunk A: nodes [0, TILES_A*64); chunk B: the rest
    k_gather<<<TILES_A * 64 / 8, 256>>>(att1, bias1, ln1g, ln1b, 0, 0);
    cudaEventRecord(s_ga, 0);
    k_gather<<<TILES_B * 64 / 8, 256>>>(att1, bias1, ln1g, ln1b, 0, TILES_A * 64);
    cudaEventRecord(s_gb, 0);
    // gemm2 on side stream, per chunk (overlaps gather chunk B)
    cudaStreamWaitEvent(s_side, s_ga, 0);
    k_gemm<<<dim3(TILES_A, 2), 256, smem2, s_side>>>(128, 0, bl2, br2);
    cudaStreamWaitEvent(s_side, s_gb, 0);
    k_gemm<<<dim3(TILES_B, 2), 256, smem2, s_side>>>(128, TILES_A, bl2, br2);
    cudaEventRecord(s_l2, s_side);
    cudaStreamWaitEvent(0, s_l2, 0);

    // layer-2 gather + pooling
    k_gather<<<NN * 32 / 256, 256>>>(att2, bias2, ln2g, ln2b, 1, 0);
    k_pool<<<BGRAPH, 128>>>(query, projW, projb, out);
}

// round 17
// speedup vs baseline: 1.0405x; 1.0405x over previous
#include <cuda_runtime.h>
#include <cuda_bf16.h>
#include <cuda_fp16.h>
#include <cstdint>
#include <cstddef>

#define NN 40000
#define EE 60000
#define RR 6
#define ETOT (EE + NN)          // 100000 edges per relation incl self-loops
#define RN (RR * NN)            // 240000
#define HC 256                  // H*C
#define HID 128
#define BGRAPH 2000
#define SCAN_NB ((RN + 1023) / 1024)   // 235
#define BM 64
#define BN 128
#define WSTH 40                 // W stage row stride in halves (32 k + 8 pad)
#define WSTAGEB (BN * WSTH * 2) // bytes per W pipeline stage (10240)
// dynamic smem upper bound: X tile (F=128, halves) + 3 W stages
#define GEMM_SMEM (BM * 136 * 2 + 3 * WSTAGEB)   // 48128 bytes

// ---------------- scratch (static device globals; no runtime allocation) ----
static __device__ __half2 g_XLh[RN * 128];   // [R][N][128] half2 (256 vals)
static __device__ __half2 g_XRh[RN * 128];   // [R][N][128] half2 (256 vals)
static __device__ float g_H[NN * HID];       // final node features (layer 2)
static __device__ __half2 g_Xch[NN * 64];    // GEMM input [N][128] as half2
static __device__ __half  g_Wch[12 * HC * HID]; // fp16 W, [rs][n][k]
static __device__ int   g_counts[RN];
static __device__ int   g_offsets[RN];
static __device__ int   g_cursor[RN];
static __device__ int   g_srcs[RR * ETOT];
static __device__ int   g_bsum[SCAN_NB];

// ---------------- CSR construction -----------------------------------------
__global__ void k_init_counts() {
    int i = blockIdx.x * blockDim.x + threadIdx.x;
    if (i < RN) g_counts[i] = 1;          // 1 == self-loop
}

__global__ void k_hist(const int* __restrict__ ei) {
    int i = blockIdx.x * blockDim.x + threadIdx.x;
    if (i >= RR * EE) return;
    int r = i / EE, e = i - r * EE;
    int dst = ei[(r * 2 + 1) * EE + e];
    atomicAdd(&g_counts[r * NN + dst], 1);
}

__global__ void k_scan1() {
    __shared__ int wsum[8];
    int tid = threadIdx.x;
    int i0 = blockIdx.x * 1024 + tid * 4;
    int4 v = make_int4(0, 0, 0, 0);
    bool ok = (i0 < RN);
    if (ok) v = *(const int4*)&g_counts[i0];
    int s0 = v.x, s1 = s0 + v.y, s2 = s1 + v.z, s3 = s2 + v.w;
    int lane = tid & 31, w = tid >> 5;
    int sc = s3;
#pragma unroll
    for (int off = 1; off < 32; off <<= 1) {
        int t = __shfl_up_sync(0xffffffffu, sc, off);
        if (lane >= off) sc += t;
    }
    if (lane == 31) wsum[w] = sc;
    __syncthreads();
    if (tid == 0) {
        int run = 0;
#pragma unroll
        for (int j = 0; j < 8; j++) { int t = wsum[j]; wsum[j] = run; run += t; }
        g_bsum[blockIdx.x] = run;
    }
    __syncthreads();
    int excl = wsum[w] + sc - s3;
    if (ok) {
        g_offsets[i0 + 0] = excl;
        g_offsets[i0 + 1] = excl + s0;
        g_offsets[i0 + 2] = excl + s1;
        g_offsets[i0 + 3] = excl + s2;
    }
}

__global__ void k_scan2() {
    __shared__ int wsum[8];
    int tid = threadIdx.x;
    int v = (tid < SCAN_NB) ? g_bsum[tid] : 0;
    int lane = tid & 31, w = tid >> 5;
    int s = v;
#pragma unroll
    for (int off = 1; off < 32; off <<= 1) {
        int t = __shfl_up_sync(0xffffffffu, s, off);
        if (lane >= off) s += t;
    }
    if (lane == 31) wsum[w] = s;
    __syncthreads();
    if (tid == 0) {
        int run = 0;
#pragma unroll
        for (int j = 0; j < 8; j++) { int t = wsum[j]; wsum[j] = run; run += t; }
    }
    __syncthreads();
    int excl = wsum[w] + s - v;
    if (tid < SCAN_NB) g_bsum[tid] = excl;
}

__global__ void k_scan3() {
    int i0 = blockIdx.x * 1024 + threadIdx.x * 4;
    if (i0 >= RN) return;
    int base = g_bsum[blockIdx.x];
    int4 o = *(const int4*)&g_offsets[i0];
    o.x += base; o.y += base; o.z += base; o.w += base;
    *(int4*)&g_offsets[i0] = o;
    *(int4*)&g_cursor[i0] = o;
}

__global__ void k_scatter(const int* __restrict__ ei) {
    int i = blockIdx.x * blockDim.x + threadIdx.x;
    if (i >= RR * ETOT) return;
    int r = i / ETOT, j = i - r * ETOT;
    int src, dst;
    if (j < EE) {
        src = ei[(r * 2 + 0) * EE + j];
        dst = ei[(r * 2 + 1) * EE + j];
    } else {
        src = j - EE; dst = src;        // self-loop
    }
    int pos = atomicAdd(&g_cursor[r * NN + dst], 1);
    g_srcs[pos] = src;
}

// ---------------- mma helpers -------------------------------------------------
__device__ __forceinline__ void mma16(float* d, const uint32_t* a, uint32_t b0, uint32_t b1) {
    asm volatile(
        "mma.sync.aligned.m16n8k16.row.col.f32.f16.f16.f32 "
        "{%0,%1,%2,%3}, {%4,%5,%6,%7}, {%8,%9}, {%0,%1,%2,%3};"
        : "+f"(d[0]), "+f"(d[1]), "+f"(d[2]), "+f"(d[3])
        : "r"(a[0]), "r"(a[1]), "r"(a[2]), "r"(a[3]), "r"(b0), "r"(b1));
}
__device__ __forceinline__ void cpasync16(uint32_t dst, const void* src) {
    asm volatile("cp.async.cg.shared.global [%0], [%1], 16;" :: "r"(dst), "l"(src));
}
__device__ __forceinline__ void ldsm4(uint32_t* r, uint32_t addr) {
    asm volatile("ldmatrix.sync.aligned.m8n8.x4.b16 {%0,%1,%2,%3}, [%4];"
        : "=r"(r[0]), "=r"(r[1]), "=r"(r[2]), "=r"(r[3]) : "r"(addr));
}

// ---------------- pre-conversion kernels ------------------------------------
// X fp32 -> g_Xch fp16 (layer-1 only; layer-2 input written by k_gather)
__global__ void k_cvtX(const float* __restrict__ X, int total4) {
    int i = blockIdx.x * blockDim.x + threadIdx.x;
    if (i >= total4) return;
    float4 v = *(const float4*)(X + (size_t)i * 4);
    __half2 h01 = __float22half2_rn(make_float2(v.x, v.y));
    __half2 h23 = __float22half2_rn(make_float2(v.z, v.w));
    uint2 u; u.x = *(unsigned*)&h01; u.y = *(unsigned*)&h23;
    *(uint2*)&g_Xch[(size_t)i * 2] = u;
}

// W [R][F][HC] (n contiguous) -> g_Wch [rs][n][k] (k contiguous), fp16
__global__ void k_cvtW(const float* __restrict__ Wl, const float* __restrict__ Wr, int F) {
    int i = blockIdx.x * blockDim.x + threadIdx.x;
    if (i >= 12 * HC * F) return;
    int rs = i / (HC * F);
    int rem = i - rs * (HC * F);
    int n = rem / F, k = rem - n * F;
    int r = (rs < RR) ? rs : rs - RR;
    const float* W = ((rs < RR) ? Wl : Wr) + ((size_t)r * F + k) * HC + n;
    g_Wch[i] = __float2half(*W);
}

// ---------------- fp16 GEMM, X-resident, 3-stage W pipeline, 1 sync/tile ----
__global__ __launch_bounds__(256, 2) void k_gemm(
    int F, const float* __restrict__ bl, const float* __restrict__ br)
{
    extern __shared__ char smemc[];
    int nhalf = blockIdx.y;
    int rowBase = blockIdx.x * BM;
    const int PRXB = (F + 8) * 2;          // X tile row stride (bytes)
    const int nk = F >> 5;                 // k-tiles per slice (1 or 4)
    const int nksh = (F == 32) ? 0 : 2;
    const int cprsh = (F == 32) ? 2 : 4;   // log2(16B chunks per X row)
    const int cmask = (F >> 3) - 1;

    uint32_t sBase = (uint32_t)__cvta_generic_to_shared(smemc);
    uint32_t wBase = sBase + BM * PRXB;
    int tid = threadIdx.x, lane = tid & 31, warp = tid >> 5;
    int wm = warp >> 2, wn = warp & 3;     // 2 x 4 warps, warp tile 32m x 32n

    const __half* Xh = (const __half*)g_Xch;
    int nxc = F >> 5;   // 16B chunks per thread (1 or 4)
#pragma unroll 2
    for (int i = 0; i < nxc; i++) {
        int c = tid + i * 256;
        int row = c >> cprsh, col = c & cmask;
        cpasync16(sBase + row * PRXB + col * 16,
                  Xh + (size_t)(rowBase + row) * F + col * 8);
    }

    auto loadW = [&](int s, int t) {
        int rs12 = t >> nksh;
        int kc = (t & (nk - 1)) << 5;      // halves
        const __half* Wp = g_Wch + (size_t)rs12 * HC * F + (size_t)nhalf * BN * F + kc;
        uint32_t ws = wBase + s * WSTAGEB;
#pragma unroll
        for (int i = 0; i < 2; i++) {
            int c = tid + i * 256;
            int row = c >> 2, col = c & 3;
            cpasync16(ws + row * (WSTH * 2) + col * 16,
                      Wp + (size_t)row * F + col * 8);
        }
        asm volatile("cp.async.commit_group;");
    };

    const int total = 12 * nk;
    loadW(0, 0);
    loadW(1, 1);

    uint32_t aBase = sBase + (wm * 32 + (lane & 15)) * PRXB + (lane >> 4) * 16;
    uint32_t bBase = wBase + (wn * 32 + (lane & 7) + ((lane >> 3) & 1) * 8) * (WSTH * 2)
                     + (lane >> 4) * 16;
    int gid = lane >> 2, tg = lane & 3;

    int t = 0;
    for (int rs12 = 0; rs12 < 12; rs12++) {
        float acc[2][4][4];
#pragma unroll
        for (int a = 0; a < 2; a++)
#pragma unroll
            for (int b = 0; b < 4; b++)
#pragma unroll
                for (int c = 0; c < 4; c++) acc[a][b][c] = 0.f;

        for (int kk = 0; kk < nk; kk++, t++) {
            if (t < total - 1) asm volatile("cp.async.wait_group 1;");
            else               asm volatile("cp.async.wait_group 0;");
            __syncthreads();
            if (t + 2 < total) loadW((t + 2) % 3, t + 2);

            uint32_t aSt = aBase + kk * 64;            // kk*32 halves
            uint32_t bSt = bBase + (t % 3) * WSTAGEB;
#pragma unroll
            for (int kt = 0; kt < 2; kt++) {
                uint32_t a0[4], a1[4];
                ldsm4(a0, aSt + kt * 32);
                ldsm4(a1, aSt + kt * 32 + 16 * PRXB);
                uint32_t b[8];
                ldsm4(b,     bSt + kt * 32);
                ldsm4(b + 4, bSt + kt * 32 + 16 * (WSTH * 2));
                mma16(acc[0][0], a0, b[0], b[2]);
                mma16(acc[1][0], a1, b[0], b[2]);
                mma16(acc[0][1], a0, b[1], b[3]);
                mma16(acc[1][1], a1, b[1], b[3]);
                mma16(acc[0][2], a0, b[4], b[6]);
                mma16(acc[1][2], a1, b[4], b[6]);
                mma16(acc[0][3], a0, b[5], b[7]);
                mma16(acc[1][3], a1, b[5], b[7]);
            }
        }

        int r = (rs12 < RR) ? rs12 : rs12 - RR;
        const float* bias = ((rs12 < RR) ? bl : br) + (size_t)r * HC + nhalf * BN;
        __half2* Y = ((rs12 < RR) ? g_XLh : g_XRh)
                     + (size_t)r * NN * 128 + nhalf * (BN / 2);
#pragma unroll
        for (int mt = 0; mt < 2; mt++) {
            int gr = rowBase + wm * 32 + mt * 16 + gid;
#pragma unroll
            for (int nt = 0; nt < 4; nt++) {
                int gc = wn * 32 + nt * 8 + 2 * tg;
                float bv0 = bias[gc], bv1 = bias[gc + 1];
                __half2 h01 = __float22half2_rn(
                    make_float2(acc[mt][nt][0] + bv0, acc[mt][nt][1] + bv1));
                __half2 h23 = __float22half2_rn(
                    make_float2(acc[mt][nt][2] + bv0, acc[mt][nt][3] + bv1));
                __stcs((unsigned*)&Y[(size_t)gr * 128 + (gc >> 1)], *(unsigned*)&h01);
                __stcs((unsigned*)&Y[(size_t)(gr + 8) * 128 + (gc >> 1)], *(unsigned*)&h23);
            }
        }
    }
}

// ---------------- GATv2 gather: warp/node, head-split lanes -----------------
// Lane l owns 8 contiguous channels of ONE head (lanes 0-15: head0, 16-31:
// head1). One LDG.128 per edge per lane; 4-level 16-lane logit reduction.
__device__ __forceinline__ void h8tof8(uint4 u, float* f) {
    float2 a = __half22float2(*(__half2*)&u.x);
    float2 b = __half22float2(*(__half2*)&u.y);
    float2 c = __half22float2(*(__half2*)&u.z);
    float2 d = __half22float2(*(__half2*)&u.w);
    f[0] = a.x; f[1] = a.y; f[2] = b.x; f[3] = b.y;
    f[4] = c.x; f[5] = c.y; f[6] = d.x; f[7] = d.y;
}

// mode 0: write fp16 result to g_Xch; mode 1: write fp32 result to g_H.
__global__ __launch_bounds__(256) void k_gather(
    const float* __restrict__ att, const float* __restrict__ bias,
    const float* __restrict__ lng, const float* __restrict__ lnb, int mode)
{
    int n = (blockIdx.x * blockDim.x + threadIdx.x) >> 5;
    int lane = threadIdx.x & 31;
    if (n >= NN) return;
    int li = lane & 15;                 // position within head half
    float o[8];
#pragma unroll
    for (int i = 0; i < 8; i++) o[i] = 0.f;

#pragma unroll 1
    for (int r = 0; r < RR; r++) {
        // XR / att: lane covers absolute channels [lane*8, lane*8+8)
        float xr[8], av[8];
        h8tof8(__ldcs((const uint4*)(g_XRh + ((size_t)(r * NN + n)) * 128 + lane * 4)), xr);
        {
            const float* ap = att + (size_t)r * HC + lane * 8;
            float4 v0 = *(const float4*)ap;
            float4 v1 = *(const float4*)(ap + 4);
            av[0] = v0.x; av[1] = v0.y; av[2] = v0.z; av[3] = v0.w;
            av[4] = v1.x; av[5] = v1.y; av[6] = v1.z; av[7] = v1.w;
        }
        int idx = r * NN + n;
        int start = g_offsets[idx];
        int deg = g_counts[idx];
        const __half2* XLr = g_XLh + (size_t)r * NN * 128;

        float s = 0.f;
        float acc[8];
#pragma unroll
        for (int i = 0; i < 8; i++) acc[i] = 0.f;

#pragma unroll 1
        for (int e = 0; e < deg; e += 2) {
            int srcA = g_srcs[start + e];
            float A[8];
            h8tof8(*(const uint4*)(XLr + (size_t)srcA * 128 + lane * 4), A);
            bool two = (e + 1 < deg);
            float B[8];
#pragma unroll
            for (int i = 0; i < 8; i++) B[i] = 0.f;
            if (two) {
                int srcB = g_srcs[start + e + 1];
                h8tof8(*(const uint4*)(XLr + (size_t)srcB * 128 + lane * 4), B);
            }
            float pa = 0.f, pb = 0.f;
#pragma unroll
            for (int i = 0; i < 8; i++) {
                float t = A[i] + xr[i];
                t = (t > 0.f) ? t : 0.2f * t;
                pa = fmaf(t, av[i], pa);
                float u = B[i] + xr[i];
                u = (u > 0.f) ? u : 0.2f * u;
                pb = fmaf(u, av[i], pb);
            }
            // 16-lane (intra-head) reduction: 4 butterfly levels
#pragma unroll
            for (int off = 1; off < 16; off <<= 1) {
                pa += __shfl_xor_sync(0xffffffffu, pa, off);
                pb += __shfl_xor_sync(0xffffffffu, pb, off);
            }
            if (!two) pb = -1e30f;
            float wa = __expf(pa), wb = __expf(pb);   // wb==0 when !two
            s += wa + wb;
#pragma unroll
            for (int i = 0; i < 8; i++) acc[i] += wa * A[i] + wb * B[i];
        }
        float invs = 0.5f / s;   // 0.5 == head average
#pragma unroll
        for (int i = 0; i < 8; i++) {
            float my = acc[i] * invs;
            float other = __shfl_xor_sync(0xffffffffu, my, 16);
            o[i] += my + other + bias[(size_t)r * HID + li * 8 + i];
        }
    }
    // tanh + LayerNorm; channels duplicated across halves => divide by 256
    float tv[8], sum = 0.f;
#pragma unroll
    for (int i = 0; i < 8; i++) { tv[i] = tanhf(o[i]); sum += tv[i]; }
#pragma unroll
    for (int off = 16; off; off >>= 1) sum += __shfl_xor_sync(0xffffffffu, sum, off);
    float mu = sum * (1.f / 256.f);
    float vv = 0.f;
    float d[8];
#pragma unroll
    for (int i = 0; i < 8; i++) { d[i] = tv[i] - mu; vv += d[i] * d[i]; }
#pragma unroll
    for (int off = 16; off; off >>= 1) vv += __shfl_xor_sync(0xffffffffu, vv, off);
    float inv = rsqrtf(vv * (1.f / 256.f) + 1e-5f);
    if (lane < 16) {   // halves hold identical data; lower half writes
        float outv[8];
#pragma unroll
        for (int i = 0; i < 8; i++)
            outv[i] = d[i] * inv * lng[li * 8 + i] + lnb[li * 8 + i];
        if (mode == 0) {
            __half2 h[4];
#pragma unroll
            for (int i = 0; i < 4; i++)
                h[i] = __float22half2_rn(make_float2(outv[2 * i], outv[2 * i + 1]));
            *(uint4*)&g_Xch[(size_t)n * 64 + li * 4] = *(uint4*)h;
        } else {
            float4 v0 = make_float4(outv[0], outv[1], outv[2], outv[3]);
            float4 v1 = make_float4(outv[4], outv[5], outv[6], outv[7]);
            *(float4*)&g_H[(size_t)n * HID + li * 8] = v0;
            *(float4*)&g_H[(size_t)n * HID + li * 8 + 4] = v1;
        }
    }
}

// ---------------- attention pooling over graphs + final projection ----------
__global__ __launch_bounds__(128) void k_pool(
    const float* __restrict__ q, const float* __restrict__ W,
    const float* __restrict__ pb, float* __restrict__ out)
{
    __shared__ float hs[20][128];
    __shared__ float sc[20];
    __shared__ float ww[20];
    __shared__ float gs[128];
    int b = blockIdx.x, t = threadIdx.x;
#pragma unroll
    for (int n = 0; n < 20; n++) hs[n][t] = g_H[(size_t)(b * 20 + n) * HID + t];
    __syncthreads();
    int lane = t & 31, w = t >> 5;
    float4 q4 = *(const float4*)&q[lane * 4];
#pragma unroll
    for (int k = 0; k < 5; k++) {
        int n = w * 5 + k;
        float4 hv = *(const float4*)&hs[n][lane * 4];
        float p = hv.x * q4.x + hv.y * q4.y + hv.z * q4.z + hv.w * q4.w;
#pragma unroll
        for (int off = 16; off; off >>= 1) p += __shfl_xor_sync(0xffffffffu, p, off);
        if (lane == 0) sc[n] = p;
    }
    __syncthreads();
    if (t < 32) {
        float v = (t < 20) ? sc[t] : -1e30f;
        float m = v;
#pragma unroll
        for (int off = 16; off; off >>= 1) m = fmaxf(m, __shfl_xor_sync(0xffffffffu, m, off));
        float e = (t < 20) ? __expf(v - m) : 0.f;
        float s = e;
#pragma unroll
        for (int off = 16; off; off >>= 1) s += __shfl_xor_sync(0xffffffffu, s, off);
        if (t < 20) ww[t] = e / s;
    }
    __syncthreads();
    float g = 0.f;
#pragma unroll
    for (int n = 0; n < 20; n++) g = fmaf(ww[n], hs[n][t], g);
    gs[t] = g;
    __syncthreads();
    float o = pb[t];
#pragma unroll 8
    for (int k = 0; k < 128; k++) o = fmaf(gs[k], W[k * 128 + t], o);
    out[(size_t)b * 128 + t] = o;
}

// ---------------- launch ----------------------------------------------------
static cudaStream_t s_side = nullptr;
static cudaEvent_t  s_fork = nullptr, s_join = nullptr;

extern "C" void kernel_launch(void* const* d_in, const int* in_sizes, int n_in,
                              void* d_out, int out_size) {
    const float* x     = (const float*)d_in[0];
    const int*   ei    = (const int*)  d_in[1];
    const float* Wl1   = (const float*)d_in[3];
    const float* bl1   = (const float*)d_in[4];
    const float* Wr1   = (const float*)d_in[5];
    const float* br1   = (const float*)d_in[6];
    const float* att1  = (const float*)d_in[7];
    const float* bias1 = (const float*)d_in[8];
    const float* Wl2   = (const float*)d_in[9];
    const float* bl2   = (const float*)d_in[10];
    const float* Wr2   = (const float*)d_in[11];
    const float* br2   = (const float*)d_in[12];
    const float* att2  = (const float*)d_in[13];
    const float* bias2 = (const float*)d_in[14];
    const float* ln1g  = (const float*)d_in[15];
    const float* ln1b  = (const float*)d_in[16];
    const float* ln2g  = (const float*)d_in[17];
    const float* ln2b  = (const float*)d_in[18];
    const float* query = (const float*)d_in[19];
    const float* projW = (const float*)d_in[20];
    const float* projb = (const float*)d_in[21];
    float* out = (float*)d_out;

    if (!s_side) {
        cudaStreamCreateWithFlags(&s_side, cudaStreamNonBlocking);
        cudaEventCreateWithFlags(&s_fork, cudaEventDisableTiming);
        cudaEventCreateWithFlags(&s_join, cudaEventDisableTiming);
    }
    cudaFuncSetAttribute(k_gemm, cudaFuncAttributeMaxDynamicSharedMemorySize, GEMM_SMEM);

    dim3 gg(NN / BM, 2);
    int smem1 = BM * (32 + 8) * 2 + 3 * WSTAGEB;     // F=32:  35840 B
    int smem2 = BM * (128 + 8) * 2 + 3 * WSTAGEB;    // F=128: 48128 B

    // ---- main stream: layer-1 GEMM path ----
    k_cvtW<<<(12 * HC * 32 + 255) / 256, 256>>>(Wl1, Wr1, 32);       // 0
    k_cvtX<<<(NN * 32 / 4 + 255) / 256, 256>>>(x, NN * 32 / 4);      // 1

    // fork side stream (CSR build + cvtW2), fully independent of GEMM path
    cudaEventRecord(s_fork, 0);
    cudaStreamWaitEvent(s_side, s_fork, 0);
    k_init_counts<<<(RN + 255) / 256, 256, 0, s_side>>>();           // 2
    k_gemm<<<gg, 256, smem1>>>(32, bl1, br1);                        // 3 (profiled)
    k_hist<<<(RR * EE + 255) / 256, 256, 0, s_side>>>(ei);
    k_scan1<<<SCAN_NB, 256, 0, s_side>>>();
    k_scan2<<<1, 256, 0, s_side>>>();
    k_scan3<<<SCAN_NB, 256, 0, s_side>>>();
    k_scatter<<<(RR * ETOT + 255) / 256, 256, 0, s_side>>>(ei);
    k_cvtW<<<(12 * HC * 128 + 255) / 256, 256, 0, s_side>>>(Wl2, Wr2, 128);
    cudaEventRecord(s_join, s_side);

    // join: gather needs gemm1 (main) + CSR (side)
    cudaStreamWaitEvent(0, s_join, 0);

    // layer 1 aggregation (fused tanh+LN) -> fp16 g_Xch
    k_gather<<<NN * 32 / 256, 256>>>(att1, bias1, ln1g, ln1b, 0);
    // layer 2
    k_gemm<<<gg, 256, smem2>>>(128, bl2, br2);
    k_gather<<<NN * 32 / 256, 256>>>(att2, bias2, ln2g, ln2b, 1);
    // pooling + projection
    k_pool<<<BGRAPH, 128>>>(query, projW, projb, out);
}